// round 6
// baseline (speedup 1.0000x reference)
#include <cuda_runtime.h>
#include <cuda_bf16.h>

// FilterLayer: out = irfft(rfft(x, ortho)*W, ortho) + x over last dim (L=12)
// == per-node circulant matvec: y[t] = sum_j h[n][(t-j) mod 12] * x[j],
// residual identity folded into tap d=0.
//
// R6: SINGLE fused kernel. R1's apply skeleton is at this pattern's practical
// ceiling (96.8us); the remaining 6.6us of the 103.4 total was the tap-build
// kernel launch + graph serialization. Each block now rebuilds the 207x12
// fp32 tap table itself (one node per thread, overlapped with the x-load
// DRAM latency) and serves taps from smem as in R5.

#define SEQ 12
#define NODES 207
#define NFREQ 7
#define WSZ (NODES * NFREQ * 2)      // 2898 floats of w
#define NTAPS (NODES * SEQ)          // 2484 floats
#define TPB 256

__device__ __constant__ float f_COS[12] = {
    1.0f,  0.8660254037844387f,  0.5f,  0.0f, -0.5f, -0.8660254037844387f,
   -1.0f, -0.8660254037844387f, -0.5f,  0.0f,  0.5f,  0.8660254037844387f
};
__device__ __constant__ float f_SIN[12] = {
    0.0f,  0.5f,  0.8660254037844387f,  1.0f,  0.8660254037844387f,  0.5f,
    0.0f, -0.5f, -0.8660254037844387f, -1.0f, -0.8660254037844387f, -0.5f
};

__global__ void __launch_bounds__(TPB) filter_fused_kernel(
    const float4* __restrict__ x,
    const float*  __restrict__ w,      // [207][7][2]
    float4* __restrict__ out)
{
    __shared__ __align__(16) float s_w[WSZ];
    __shared__ __align__(16) float s_H[NTAPS];

    const int tid = threadIdx.x;
    const int r   = blockIdx.x * TPB + tid;   // one row per thread, exact grid

    // Coalesced copy of w into smem (~12 scalar LDGs per thread).
    #pragma unroll
    for (int i = tid; i < WSZ; i += TPB) s_w[i] = __ldg(w + i);

    // Issue this thread's row loads now so their DRAM latency covers the
    // tap-table build below.
    const size_t g = (size_t)r * 3;
    const float4 a = __ldg(x + g + 0);
    const float4 b = __ldg(x + g + 1);
    const float4 c = __ldg(x + g + 2);

    __syncthreads();   // s_w ready

    // One node per thread (threads 0..206): build 12 circulant taps in fp32.
    if (tid < NODES) {
        const float* wn = s_w + tid * (NFREQ * 2);
        const float w0  = wn[0];
        const float w6r = wn[12];
        float wr[6], wi[6];
        #pragma unroll
        for (int k = 1; k <= 5; k++) {
            wr[k] = 2.0f * wn[2 * k];
            wi[k] = -2.0f * wn[2 * k + 1];
        }
        float t[SEQ];
        #pragma unroll
        for (int d = 0; d < SEQ; d++) {
            float acc = w0 + ((d & 1) ? -w6r : w6r);
            #pragma unroll
            for (int k = 1; k <= 5; k++) {
                const int m = (k * d) % 12;          // compile-time
                acc = fmaf(wr[k], f_COS[m], acc);
                acc = fmaf(wi[k], f_SIN[m], acc);
            }
            t[d] = acc * (1.0f / 12.0f);
        }
        t[0] += 1.0f;    // fold residual identity
        float4* dst = reinterpret_cast<float4*>(s_H + tid * SEQ);
        dst[0] = make_float4(t[0], t[1], t[2],  t[3]);
        dst[1] = make_float4(t[4], t[5], t[6],  t[7]);
        dst[2] = make_float4(t[8], t[9], t[10], t[11]);
    }
    __syncthreads();   // s_H ready

    // Per-thread taps: 3x conflict-free LDS.128 (48B stride).
    const int n = r % NODES;
    const float4* hp = reinterpret_cast<const float4*>(s_H + n * SEQ);
    const float4 h0 = hp[0], h1 = hp[1], h2 = hp[2];
    const float h[SEQ] = { h0.x, h0.y, h0.z, h0.w,
                           h1.x, h1.y, h1.z, h1.w,
                           h2.x, h2.y, h2.z, h2.w };

    const float xv[SEQ] = { a.x, a.y, a.z, a.w,
                            b.x, b.y, b.z, b.w,
                            c.x, c.y, c.z, c.w };

    float y[SEQ];
    #pragma unroll
    for (int t = 0; t < SEQ; t++) {
        float s = 0.0f;
        #pragma unroll
        for (int j = 0; j < SEQ; j++)
            s = fmaf(h[(t - j + SEQ) % SEQ], xv[j], s);   // compile-time index
        y[t] = s;
    }

    out[g + 0] = make_float4(y[0], y[1], y[2],  y[3]);
    out[g + 1] = make_float4(y[4], y[5], y[6],  y[7]);
    out[g + 2] = make_float4(y[8], y[9], y[10], y[11]);
}

extern "C" void kernel_launch(void* const* d_in, const int* in_sizes, int n_in,
                              void* d_out, int out_size) {
    const float* x = (const float*)d_in[0];   // [1024,32,207,12] fp32
    const float* w = (const float*)d_in[1];   // [1,207,7,2] fp32

    const int nrows = out_size / SEQ;         // 6,782,976 = 26496 * 256 exactly
    const int blocks = (nrows + TPB - 1) / TPB;
    filter_fused_kernel<<<blocks, TPB>>>(
        reinterpret_cast<const float4*>(x),
        w,
        reinterpret_cast<float4*>(d_out));
}

// round 7
// speedup vs baseline: 1.2066x; 1.2066x over previous
#include <cuda_runtime.h>
#include <cuda_bf16.h>

// FilterLayer: out = irfft(rfft(x, ortho)*W, ortho) + x over last dim (L=12)
// == per-node circulant matvec: y[t] = sum_j h[n][(t-j) mod 12] * x[j],
// residual identity folded into tap d=0.
//
// R7 = R1's apply body (best measured: 96.8us, DRAM 78%) unchanged, plus:
//  - PDL: apply launched with programmatic stream serialization so its grid
//    dispatches concurrently with the tiny tap-build kernel; apply issues its
//    x loads, then cudaGridDependencySynchronize(), then reads taps.
//  - build kernel reshaped to one-tap-per-thread (10 x 256).
//  - __stcs streaming stores (output never re-read).

#define SEQ 12
#define NODES 207
#define NFREQ 7
#define NTAPS (NODES * SEQ)          // 2484
#define TPB 256

__device__ __align__(16) float g_H[NTAPS];

__device__ __constant__ double c_COS[12] = {
    1.0,  0.8660254037844387,  0.5,  0.0, -0.5, -0.8660254037844387,
   -1.0, -0.8660254037844387, -0.5,  0.0,  0.5,  0.8660254037844387
};
__device__ __constant__ double c_SIN[12] = {
    0.0,  0.5,  0.8660254037844387,  1.0,  0.8660254037844387,  0.5,
    0.0, -0.5, -0.8660254037844387, -1.0, -0.8660254037844387, -0.5
};

__global__ void build_taps_kernel(const float* __restrict__ w /*[207][7][2]*/) {
    int i = blockIdx.x * blockDim.x + threadIdx.x;
    if (i >= NTAPS) return;
    int n = i / SEQ, d = i % SEQ;
    const float* wn = w + n * (NFREQ * 2);
    double acc = (double)wn[0];
    acc += ((d & 1) ? -1.0 : 1.0) * (double)wn[2 * 6];
    #pragma unroll
    for (int k = 1; k <= 5; k++) {
        int m = (k * d) % 12;
        acc += 2.0 * ((double)wn[2 * k] * c_COS[m] - (double)wn[2 * k + 1] * c_SIN[m]);
    }
    float h = (float)(acc / 12.0);
    if (d == 0) h += 1.0f;   // fold residual identity
    g_H[i] = h;
}

__global__ void __launch_bounds__(TPB) filter_apply_kernel(
    const float4* __restrict__ x, float4* __restrict__ out)
{
    const int r = blockIdx.x * TPB + threadIdx.x;   // one row per thread

    // x loads do not depend on the build kernel — issue before grid sync.
    const size_t g = (size_t)r * 3;
    const float4 a = __ldg(x + g + 0);
    const float4 b = __ldg(x + g + 1);
    const float4 c = __ldg(x + g + 2);

#if __CUDA_ARCH__ >= 900
    cudaGridDependencySynchronize();   // taps ready beyond this point
#endif

    const int n = r % NODES;
    const float4* Hv = reinterpret_cast<const float4*>(g_H + n * SEQ);
    const float4 h0 = __ldg(Hv + 0);
    const float4 h1 = __ldg(Hv + 1);
    const float4 h2 = __ldg(Hv + 2);
    const float h[SEQ] = { h0.x, h0.y, h0.z, h0.w,
                           h1.x, h1.y, h1.z, h1.w,
                           h2.x, h2.y, h2.z, h2.w };

    const float xv[SEQ] = { a.x, a.y, a.z, a.w,
                            b.x, b.y, b.z, b.w,
                            c.x, c.y, c.z, c.w };

    float y[SEQ];
    #pragma unroll
    for (int t = 0; t < SEQ; t++) {
        float s = 0.0f;
        #pragma unroll
        for (int j = 0; j < SEQ; j++)
            s = fmaf(h[(t - j + SEQ) % SEQ], xv[j], s);   // compile-time index
        y[t] = s;
    }

    // Streaming stores: output is write-once, never re-read.
    __stcs(out + g + 0, make_float4(y[0], y[1], y[2],  y[3]));
    __stcs(out + g + 1, make_float4(y[4], y[5], y[6],  y[7]));
    __stcs(out + g + 2, make_float4(y[8], y[9], y[10], y[11]));
}

extern "C" void kernel_launch(void* const* d_in, const int* in_sizes, int n_in,
                              void* d_out, int out_size) {
    const float* x = (const float*)d_in[0];   // [1024,32,207,12] fp32
    const float* w = (const float*)d_in[1];   // [1,207,7,2] fp32

    build_taps_kernel<<<(NTAPS + TPB - 1) / TPB, TPB>>>(w);

    const int nrows = out_size / SEQ;         // 6,782,976 = 26496 * 256 exactly
    const int blocks = (nrows + TPB - 1) / TPB;

    // PDL launch: allow this grid to begin while build_taps_kernel finishes;
    // the device-side cudaGridDependencySynchronize provides the ordering.
    cudaLaunchConfig_t cfg = {};
    cfg.gridDim  = dim3((unsigned)blocks, 1, 1);
    cfg.blockDim = dim3(TPB, 1, 1);
    cfg.dynamicSmemBytes = 0;
    cfg.stream = 0;
    cudaLaunchAttribute attr[1];
    attr[0].id = cudaLaunchAttributeProgrammaticStreamSerialization;
    attr[0].val.programmaticStreamSerializationAllowed = 1;
    cfg.attrs = attr;
    cfg.numAttrs = 1;

    const float4* x4 = reinterpret_cast<const float4*>(x);
    float4* o4 = reinterpret_cast<float4*>(d_out);
    cudaError_t e = cudaLaunchKernelEx(&cfg, filter_apply_kernel, x4, o4);
    if (e != cudaSuccess) {
        // Fallback: plain serialized launch (still correct).
        filter_apply_kernel<<<blocks, TPB>>>(x4, o4);
    }
}